// round 2
// baseline (speedup 1.0000x reference)
#include <cuda_runtime.h>
#include <math.h>

// Problem constants (fixed by the dataset)
#define MAXN   100000
#define FIN    128
#define HIDD   16
#define COUT   10
#define CPAD   12          // layer-2 row padded to 12 floats (48B, float4-aligned)

// -------- device scratch (static: no allocation allowed) --------
__device__ float g_h0 [MAXN * HIDD];   // x @ W1[0]
__device__ float g_d1 [MAXN * HIDD];   // x @ (W1[1]-W1[0])
__device__ float g_r1 [MAXN * HIDD];   // x @ root1 + b1
__device__ float g_A1 [MAXN * HIDD];   // edge aggregation layer 1
__device__ float g_h  [MAXN * HIDD];   // elu(A1/deg + r1)
__device__ float g_h0b[MAXN * CPAD];   // h @ W2[0]          (padded)
__device__ float g_d2 [MAXN * CPAD];   // h @ (W2[1]-W2[0])  (padded)
__device__ float g_r2 [MAXN * CPAD];   // h @ root2 + b2     (padded)
__device__ float g_A2 [MAXN * CPAD];   // edge aggregation layer 2
__device__ float g_deg[MAXN];
__device__ int   g_is64;

// -------- detect int64 vs int32 edge_index (uniform device flag) --------
__global__ void detect_idx_kernel(const long long* __restrict__ ei, int n) {
    if (blockIdx.x == 0 && threadIdx.x == 0) {
        int is64 = 1;
        for (int i = 0; i < 64; i++) {
            long long v = ei[i];
            if (v < 0 || v >= (long long)n) { is64 = 0; break; }
        }
        g_is64 = is64;
    }
}

// -------- layer-1 node GEMM: 48 columns of 128-dim dots --------
// Also zeroes A1 and deg (fused init).
__global__ void __launch_bounds__(256)
gemm1_kernel(const float* __restrict__ x,
             const float* __restrict__ W1,
             const float* __restrict__ root1,
             const float* __restrict__ b1,
             int n) {
    __shared__ float sW[48 * FIN];     // 24 KB: [j][k] layout
    for (int i = threadIdx.x; i < 48 * FIN; i += blockDim.x) {
        int j = i >> 7;      // 0..47
        int k = i & 127;     // 0..127
        float v;
        if (j < 16)       v = W1[k * 16 + j];
        else if (j < 32)  v = W1[2048 + k * 16 + (j - 16)] - W1[k * 16 + (j - 16)];
        else              v = root1[k * 16 + (j - 32)];
        sW[j * FIN + k] = v;
    }
    __syncthreads();

    int node = blockIdx.x * blockDim.x + threadIdx.x;
    if (node >= n) return;

    const float4* xr  = (const float4*)(x + (size_t)node * FIN);
    const float4* sW4 = (const float4*)sW;

    float acc[48];
#pragma unroll
    for (int j = 0; j < 48; j++) acc[j] = 0.f;

#pragma unroll 4
    for (int kc = 0; kc < FIN / 4; kc++) {
        float4 xv = xr[kc];
#pragma unroll
        for (int j = 0; j < 48; j++) {
            float4 wv = sW4[j * (FIN / 4) + kc];   // uniform across warp -> smem broadcast
            acc[j] += xv.x * wv.x + xv.y * wv.y + xv.z * wv.z + xv.w * wv.w;
        }
    }

    float* h0 = g_h0 + (size_t)node * HIDD;
    float* d1 = g_d1 + (size_t)node * HIDD;
    float* r1 = g_r1 + (size_t)node * HIDD;
    float* A1 = g_A1 + (size_t)node * HIDD;
#pragma unroll
    for (int j = 0; j < 16; j++) {
        h0[j] = acc[j];
        d1[j] = acc[16 + j];
        r1[j] = acc[32 + j] + b1[j];
        A1[j] = 0.f;
    }
    g_deg[node] = 0.f;
}

// -------- vector reduction helper --------
__device__ __forceinline__ void red_add_v4(float* p, float4 v) {
    asm volatile("red.global.add.v4.f32 [%0], {%1, %2, %3, %4};"
                 :: "l"(__cvta_generic_to_global(p)),
                    "f"(v.x), "f"(v.y), "f"(v.z), "f"(v.w)
                 : "memory");
}

// -------- layer-1 edge pass: gather h0/d1 rows, FMA, scatter-add --------
__global__ void __launch_bounds__(256)
edge1_kernel(const long long* __restrict__ ei,
             const float* __restrict__ ea, int E) {
    int e = blockIdx.x * blockDim.x + threadIdx.x;
    if (e >= E) return;
    const int is64 = g_is64;
    int s, t;
    if (is64) {
        s = (int)ei[e];
        t = (int)ei[(size_t)E + e];
    } else {
        const int* ei32 = (const int*)ei;
        s = ei32[e];
        t = ei32[(size_t)E + e];
    }
    float w = ea[e];
    const float4* a = (const float4*)(g_h0 + (size_t)s * HIDD);
    const float4* b = (const float4*)(g_d1 + (size_t)s * HIDD);
    float* out = g_A1 + (size_t)t * HIDD;
#pragma unroll
    for (int q = 0; q < 4; q++) {
        float4 av = a[q];
        float4 bv = b[q];
        float4 m;
        m.x = fmaf(w, bv.x, av.x);
        m.y = fmaf(w, bv.y, av.y);
        m.z = fmaf(w, bv.z, av.z);
        m.w = fmaf(w, bv.w, av.w);
        red_add_v4(out + q * 4, m);
    }
    atomicAdd(&g_deg[t], 1.0f);
}

// -------- layer-1 epilogue: h = elu(A1/deg + r1) --------
__global__ void __launch_bounds__(256)
node1_kernel(int n) {
    int i = blockIdx.x * blockDim.x + threadIdx.x;
    if (i >= n * HIDD) return;
    float dg = fmaxf(g_deg[i >> 4], 1.0f);
    float v = g_A1[i] / dg + g_r1[i];
    g_h[i] = (v > 0.f) ? v : expm1f(v);
}

// -------- layer-2 node GEMM: 30 columns of 16-dim dots (fused A2/pad init) ----
__global__ void __launch_bounds__(256)
gemm2_kernel(const float* __restrict__ W2,
             const float* __restrict__ root2,
             const float* __restrict__ b2,
             int n) {
    __shared__ float sW[30 * HIDD];    // [j][k]
    __shared__ float sB[COUT];
    for (int i = threadIdx.x; i < 30 * HIDD; i += blockDim.x) {
        int j = i >> 4;      // 0..29
        int k = i & 15;
        float v;
        if (j < 10)       v = W2[k * 10 + j];
        else if (j < 20)  v = W2[160 + k * 10 + (j - 10)] - W2[k * 10 + (j - 10)];
        else              v = root2[k * 10 + (j - 20)];
        sW[j * HIDD + k] = v;
    }
    if (threadIdx.x < COUT) sB[threadIdx.x] = b2[threadIdx.x];
    __syncthreads();

    int node = blockIdx.x * blockDim.x + threadIdx.x;
    if (node >= n) return;

    const float4* hr  = (const float4*)(g_h + (size_t)node * HIDD);
    const float4* sW4 = (const float4*)sW;
    float4 hv[4];
#pragma unroll
    for (int q = 0; q < 4; q++) hv[q] = hr[q];

    float acc[30];
#pragma unroll
    for (int j = 0; j < 30; j++) acc[j] = 0.f;
#pragma unroll
    for (int kc = 0; kc < 4; kc++) {
#pragma unroll
        for (int j = 0; j < 30; j++) {
            float4 wv = sW4[j * 4 + kc];
            acc[j] += hv[kc].x * wv.x + hv[kc].y * wv.y + hv[kc].z * wv.z + hv[kc].w * wv.w;
        }
    }

    float* h0b = g_h0b + (size_t)node * CPAD;
    float* d2  = g_d2  + (size_t)node * CPAD;
    float* r2  = g_r2  + (size_t)node * CPAD;
    float* A2  = g_A2  + (size_t)node * CPAD;
#pragma unroll
    for (int c = 0; c < COUT; c++) {
        h0b[c] = acc[c];
        d2[c]  = acc[10 + c];
        r2[c]  = acc[20 + c] + sB[c];
        A2[c]  = 0.f;
    }
#pragma unroll
    for (int c = COUT; c < CPAD; c++) {      // zero the pad lanes
        h0b[c] = 0.f; d2[c] = 0.f; r2[c] = 0.f; A2[c] = 0.f;
    }
}

// -------- layer-2 edge pass (padded rows of 12) --------
__global__ void __launch_bounds__(256)
edge2_kernel(const long long* __restrict__ ei,
             const float* __restrict__ ea, int E) {
    int e = blockIdx.x * blockDim.x + threadIdx.x;
    if (e >= E) return;
    const int is64 = g_is64;
    int s, t;
    if (is64) {
        s = (int)ei[e];
        t = (int)ei[(size_t)E + e];
    } else {
        const int* ei32 = (const int*)ei;
        s = ei32[e];
        t = ei32[(size_t)E + e];
    }
    float w = ea[e];
    const float4* a = (const float4*)(g_h0b + (size_t)s * CPAD);
    const float4* b = (const float4*)(g_d2  + (size_t)s * CPAD);
    float* out = g_A2 + (size_t)t * CPAD;
#pragma unroll
    for (int q = 0; q < 3; q++) {
        float4 av = a[q];
        float4 bv = b[q];
        float4 m;
        m.x = fmaf(w, bv.x, av.x);
        m.y = fmaf(w, bv.y, av.y);
        m.z = fmaf(w, bv.z, av.z);
        m.w = fmaf(w, bv.w, av.w);
        red_add_v4(out + q * 4, m);
    }
}

// -------- final epilogue: out = A2/deg + r2 (unpadded 10-wide output) --------
__global__ void __launch_bounds__(256)
node2_kernel(float* __restrict__ out, int n) {
    int i = blockIdx.x * blockDim.x + threadIdx.x;
    if (i >= n * COUT) return;
    int node = i / COUT;
    int c    = i - node * COUT;
    float dg = fmaxf(g_deg[node], 1.0f);
    out[i] = g_A2[(size_t)node * CPAD + c] / dg + g_r2[(size_t)node * CPAD + c];
}

extern "C" void kernel_launch(void* const* d_in, const int* in_sizes, int n_in,
                              void* d_out, int out_size) {
    const float*     x     = (const float*)d_in[0];
    const long long* ei    = (const long long*)d_in[1];
    const float*     ea    = (const float*)d_in[2];
    const float*     W1    = (const float*)d_in[3];
    const float*     root1 = (const float*)d_in[4];
    const float*     b1    = (const float*)d_in[5];
    const float*     W2    = (const float*)d_in[6];
    const float*     root2 = (const float*)d_in[7];
    const float*     b2    = (const float*)d_in[8];
    float* out = (float*)d_out;

    int n = in_sizes[0] / FIN;       // 100000
    int E = in_sizes[2];             // 1600000 (edge_attr is (E,1))

    detect_idx_kernel<<<1, 32>>>(ei, n);
    gemm1_kernel<<<(n + 255) / 256, 256>>>(x, W1, root1, b1, n);
    edge1_kernel<<<(E + 255) / 256, 256>>>(ei, ea, E);
    node1_kernel<<<(n * HIDD + 255) / 256, 256>>>(n);
    gemm2_kernel<<<(n + 255) / 256, 256>>>(W2, root2, b2, n);
    edge2_kernel<<<(E + 255) / 256, 256>>>(ei, ea, E);
    node2_kernel<<<(n * COUT + 255) / 256, 256>>>(out, n);
}